// round 17
// baseline (speedup 1.0000x reference)
#include <cuda_runtime.h>
#include <cstdint>

#define NN 96
#define DD 64
#define TPB 256
#define NCHUNK 624   // sum over U of ceil((U+1)/8)
#define MAXT 60
#define NBLK_A 192           // phase A: 96 X0 + 96 adj
#define NBLK_B 192           // phase B: 2 per U
#define GRID_TOTAL (NBLK_A + NBLK_B + NCHUNK)

// Scratch (allocation-free rule): device globals, recomputed deterministically every launch.
__device__ float g_X0[NN * DD];
__device__ float g_P0[NN * NN * DD];
__device__ unsigned g_mask[NN * 3];
__device__ __align__(16) unsigned char g_nbr[NN * NN];
__device__ int g_done0;        // phase-A completion counter (target NBLK_A)
__device__ int g_flagU[NN];    // per-U phase-B completion (target 2)

__device__ __forceinline__ unsigned wmask(int n, int w) {
    int m = n - (w << 5);
    if (m <= 0) return 0u;
    if (m >= 32) return 0xffffffffu;
    return (1u << m) - 1u;
}

__device__ __forceinline__ int cumc(int U) {   // 8-chunks before U
    int a = U >> 3, r = U & 7;
    return (a + 1) * (4 * a + r);
}

__global__ void reset_kernel() {
    int t = threadIdx.x;
    if (t < NN) g_flagU[t] = 0;
    if (t == NN) g_done0 = 0;
}

// ---- shared-memory overlays (union of the three phases) ----
struct SmemPair {
    unsigned mask[NN * 3];
    float s0[NN], s1d[NN];
    float x[NN * DD];
    float4 metaA[8][MAXT];
    uint4  metaB[8][MAXT];
};
struct SmemP0 {
    unsigned mask[NN * 3];
    float s[NN];
    float yb[(NN + 1) * DD];
};
struct SmemA {
    float zr[DD];
    unsigned smk[3];
    unsigned char snb[NN];
};

__global__ void __launch_bounds__(TPB) mega_kernel(const float* __restrict__ z,
                                                   const float* __restrict__ adj,
                                                   const float* __restrict__ W1,
                                                   const float* __restrict__ W2,
                                                   float* __restrict__ out) {
    __shared__ __align__(16) unsigned char SMRAW[sizeof(SmemPair)];
    int bid = blockIdx.x;
    int tid = threadIdx.x;

    if (bid < NBLK_A) {
        // ================= PHASE A: X0 rows / adjacency rows =================
        SmemA& S = *reinterpret_cast<SmemA*>(SMRAW);
        if (bid < NN) {
            int row = bid, c = tid;
            if (c < DD) S.zr[c] = z[row * DD + c];
            __syncthreads();
            if (c < DD) {
                float acc = 0.f;
#pragma unroll
                for (int k = 0; k < DD; k++) acc += S.zr[k] * W1[k * DD + c];
                g_X0[row * DD + c] = acc;
            }
        } else {
            int row = bid - NN;
            int t = tid;
            bool f = (t < NN) && (adj[row * NN + t] != 0.0f);
            unsigned bal = __ballot_sync(0xffffffffu, f);
            if (t < NN && (t & 31) == 0) { S.smk[t >> 5] = bal; g_mask[row * 3 + (t >> 5)] = bal; }
            if (t < NN) S.snb[t] = 96;
            __syncthreads();
            if (t < NN) {
                unsigned m0 = S.smk[0], m1 = S.smk[1], m2 = S.smk[2];
                int w = t >> 5, l = t & 31;
                unsigned lm = (1u << l) - 1u;
                unsigned mw = (w == 0) ? m0 : ((w == 1) ? m1 : m2);
                int off = ((w > 0) ? __popc(m0) : 0) + ((w > 1) ? __popc(m1) : 0) + __popc(mw & lm);
                if (f) S.snb[off] = (unsigned char)t;
            }
            __syncthreads();
            if (t < NN) g_nbr[row * NN + t] = S.snb[t];
        }
        __syncthreads();
        __threadfence();
        if (tid == 0) atomicAdd(&g_done0, 1);
        return;
    }

    if (bid < NBLK_A + NBLK_B) {
        // ================= PHASE B: P0[U] (2 blocks per U, U descending) =====
        int lb = bid - NBLK_A;
        int U = 95 - (lb >> 1);          // heavy U first
        int half = lb & 1;
        SmemP0& S = *reinterpret_cast<SmemP0*>(SMRAW);

        if (tid == 0) {
            while (*(volatile int*)&g_done0 != NBLK_A) __nanosleep(64);
            __threadfence();
        }
        __syncthreads();

        int ln = tid & 15, hw = tid >> 4;
        for (int q = tid; q < NN * 3; q += TPB) S.mask[q] = g_mask[q];
        __syncthreads();
        if (tid < NN) {
            int deg = 1 + __popc(S.mask[tid * 3] & wmask(U, 0))
                        + __popc(S.mask[tid * 3 + 1] & wmask(U, 1))
                        + __popc(S.mask[tid * 3 + 2] & wmask(U, 2));
            S.s[tid] = rsqrtf((float)deg);
        }
        __syncthreads();
        const float4* x04 = (const float4*)g_X0;
        for (int q = tid; q < (NN + 1) * 16; q += TPB) {
            int row = q >> 4;
            float4 v = make_float4(0.f, 0.f, 0.f, 0.f);
            if (row < U) {
                v = x04[q];
                float s = S.s[row];
                v.x *= s; v.y *= s; v.z *= s; v.w *= s;
            }
            ((float4*)S.yb)[q] = v;
        }
        __syncthreads();

        const float4* yb4 = (const float4*)S.yb;
        float4* p04 = (float4*)g_P0;
        for (int m = hw + (half << 4); m < U; m += 32) {
            int cnt = __popc(S.mask[m * 3] & wmask(U, 0))
                    + __popc(S.mask[m * 3 + 1] & wmask(U, 1))
                    + __popc(S.mask[m * 3 + 2] & wmask(U, 2));
            float4 a = yb4[m * 16 + ln];
            const unsigned char* lst = &g_nbr[m * NN];
            int c4 = (cnt + 3) & ~3;
            for (int q = 0; q < c4; q += 4) {
                unsigned pk = *(const unsigned*)(lst + q);
                float4 y0 = yb4[((pk & 255u) << 4) + ln];
                a.x += y0.x; a.y += y0.y; a.z += y0.z; a.w += y0.w;
                float4 y1 = yb4[(((pk >> 8) & 255u) << 4) + ln];
                a.x += y1.x; a.y += y1.y; a.z += y1.z; a.w += y1.w;
                float4 y2 = yb4[(((pk >> 16) & 255u) << 4) + ln];
                a.x += y2.x; a.y += y2.y; a.z += y2.z; a.w += y2.w;
                float4 y3 = yb4[((pk >> 24) << 4) + ln];
                a.x += y3.x; a.y += y3.y; a.z += y3.z; a.w += y3.w;
            }
            p04[(U * NN + m) * 16 + ln] = a;
        }
        __syncthreads();
        __threadfence();
        if (tid == 0) atomicAdd(&g_flagU[U], 1);
        return;
    }

    // ================= PHASE C: pair evaluation (R15 body) ===================
    SmemPair& S = *reinterpret_cast<SmemPair*>(SMRAW);
    int b = (NCHUNK - 1) - (bid - NBLK_A - NBLK_B);
    int a0 = (int)(sqrtf((float)b) * 0.5f);
    int U = 8 * a0;
    if (U > 95) U = 95;
    while (U < 95 && cumc(U + 1) <= b) ++U;
    while (U > 0 && cumc(U) > b) --U;
    int Lbase = (b - cumc(U)) * 8;

    if (tid == 0) {
        while (*(volatile int*)&g_flagU[U] != 2) __nanosleep(64);
        __threadfence();
    }
    __syncthreads();

    int lane = tid & 31, warp = tid >> 5;

    for (int q = tid; q < NN * 3; q += TPB) S.mask[q] = g_mask[q];
    __syncthreads();

    unsigned uw0 = S.mask[U * 3 + 0] & wmask(U, 0);
    unsigned uw1 = S.mask[U * 3 + 1] & wmask(U, 1);
    unsigned uw2 = S.mask[U * 3 + 2] & wmask(U, 2);
    int cntU = __popc(uw0) + __popc(uw1) + __popc(uw2);

    if (tid < NN) {
        int m = tid;
        int deg = 1 + __popc(S.mask[m * 3] & wmask(U, 0))
                    + __popc(S.mask[m * 3 + 1] & wmask(U, 1))
                    + __popc(S.mask[m * 3 + 2] & wmask(U, 2));
        float s0 = rsqrtf((float)deg);
        S.s0[m] = s0;
        S.s1d[m] = rsqrtf((float)(deg + 1)) - s0;
    }
    const float4* x04 = (const float4*)g_X0;
    for (int q = tid >> 4; q < cntU; q += 16) {
        int bb = g_nbr[U * NN + q];
        ((float4*)S.x)[bb * 16 + (tid & 15)] = x04[bb * 16 + (tid & 15)];
    }
    __syncthreads();

    int L = Lbase + warp;
    if (L > U) return;

    unsigned Dw0 = S.mask[U * 3 + 0] & wmask(L, 0);
    unsigned Dw1 = S.mask[U * 3 + 1] & wmask(L, 1);
    unsigned Dw2 = S.mask[U * 3 + 2] & wmask(L, 2);
    int nD = __popc(Dw0) + __popc(Dw1) + __popc(Dw2);
    float sU = rsqrtf(1.0f + (float)nD);
    float sL0 = S.s0[L];

    int ln = lane & 15, h = lane >> 4;
    const float4* W14 = (const float4*)W1;
    float4 w2v = __ldg(&((const float4*)W2)[ln]);
    float4 paV = __ldg(&W14[64 * 16 + ln]);
    float4 pbV = __ldg(&W14[65 * 16 + ln]);
    float4 dv = make_float4(pbV.x - paV.x, pbV.y - paV.y, pbV.z - paV.z, pbV.w - paV.w);
    float4 yU = __ldg(&x04[U * 16 + ln]);
    yU.x += pbV.x; yU.y += pbV.y; yU.z += pbV.z; yU.w += pbV.w;
    if (L == U) { yU.x += paV.x; yU.y += paV.y; yU.z += paV.z; yU.w += paV.w; }

    // fold the U-target: PU = sum_{b in D} (s1d_b + s0_b) x_b + sU*yU
    float4 PU = make_float4(0.f, 0.f, 0.f, 0.f);
#pragma unroll
    for (int w = 0; w < 3; w++) {
        unsigned dm = (w == 0) ? Dw0 : ((w == 1) ? Dw1 : Dw2);
        while (dm) {
            int bb = __ffs(dm) - 1;
            dm &= dm - 1;
            bb += w << 5;
            float wt = S.s1d[bb] + S.s0[bb];
            float4 xb = ((const float4*)S.x)[bb * 16 + ln];
            PU.x += wt * xb.x; PU.y += wt * xb.y; PU.z += wt * xb.z; PU.w += wt * xb.w;
        }
    }
    PU.x += sU * yU.x; PU.y += sU * yU.y; PU.z += sU * yU.z; PU.w += sU * yU.w;

    unsigned t0 = ((S.mask[L * 3 + 0] | ((L < 32) ? (1u << L) : 0u)) & wmask(U, 0)) | Dw0;
    unsigned t1 = ((S.mask[L * 3 + 1] | ((L >= 32 && L < 64) ? (1u << (L & 31)) : 0u)) & wmask(U, 1)) | Dw1;
    unsigned t2 = ((S.mask[L * 3 + 2] | ((L >= 64) ? (1u << (L & 31)) : 0u)) & wmask(U, 2)) | Dw2;
    if (U < 32) t0 |= 1u << U; else if (U < 64) t1 |= 1u << (U & 31); else t2 |= 1u << (U & 31);

    unsigned lm = (1u << lane) - 1u;
    int c0 = __popc(t0), c1 = __popc(t1);
    int nT = c0 + c1 + __popc(t2);
#pragma unroll
    for (int w = 0; w < 3; w++) {
        unsigned tw = (w == 0) ? t0 : ((w == 1) ? t1 : t2);
        unsigned bit = 1u << lane;
        if (tw & bit) {
            int base = (w > 0 ? c0 : 0) + (w > 1 ? c1 : 0);
            int pos = base + __popc(tw & lm);
            int m = (w << 5) + lane;
            bool isU = (m == U);
            unsigned Dww = (w == 0) ? Dw0 : ((w == 1) ? Dw1 : Dw2);
            bool inD  = !isU && ((Dww & bit) != 0);
            bool inNL = (m == L) || ((S.mask[L * 3 + w] & bit) != 0);
            float sm = isU ? sU : (S.s0[m] + (inD ? S.s1d[m] : 0.f));
            float c  = (L == U) ? 0.f : (isU ? -sU : ((inNL ? sL0 : 0.f) - (inD ? sU : 0.f)));
            float coef = isU ? ((L == U) ? 2.f * sU : sU)
                             : ((inNL ? sL0 : 0.f) + (inD ? sU : 0.f));
            coef *= sm;
            int off = isU ? -1 : (U * NN + m) * 16;
            unsigned cm0 = 0, cm1 = 0, cm2 = 0, flags = 0;
            if (!isU) {
                cm0 = (S.mask[m * 3 + 0] | ((w == 0) ? bit : 0u)) & Dw0;
                cm1 = (S.mask[m * 3 + 1] | ((w == 1) ? bit : 0u)) & Dw1;
                cm2 = (S.mask[m * 3 + 2] | ((w == 2) ? bit : 0u)) & Dw2;
                flags = (inD ? 1u : 0u) | ((inNL && L != U) ? 2u : 0u);
            }
            S.metaA[warp][pos] = make_float4(sm, c, coef, __int_as_float(off));
            S.metaB[warp][pos] = make_uint4(cm0, cm1, cm2, flags);
        }
    }
    __syncwarp();

    const float4* p04 = (const float4*)g_P0;
    float acc1 = 0.f, acc2 = 0.f;
    int rounds = (nT + 1) >> 1;

    for (int r = 0; r < rounds; r++) {
        int idx = 2 * r + h;
        bool act = (idx < nT);
        int ix = act ? idx : 0;
        float4 ma = S.metaA[warp][ix];
        uint4  mb = S.metaB[warp][ix];
        int off = __float_as_int(ma.w);

        float4 P;
        if (off >= 0) P = __ldg(&p04[off + ln]);
        else          P = PU;

        unsigned cm = mb.x;
        while (cm) {
            int bb = __ffs(cm) - 1; cm &= cm - 1;
            float4 xb = ((const float4*)S.x)[bb * 16 + ln];
            float wt = S.s1d[bb];
            P.x += wt * xb.x; P.y += wt * xb.y; P.z += wt * xb.z; P.w += wt * xb.w;
        }
        cm = mb.y;
        while (cm) {
            int bb = __ffs(cm) + 31; cm &= cm - 1;
            float4 xb = ((const float4*)S.x)[bb * 16 + ln];
            float wt = S.s1d[bb];
            P.x += wt * xb.x; P.y += wt * xb.y; P.z += wt * xb.z; P.w += wt * xb.w;
        }
        cm = mb.z;
        while (cm) {
            int bb = __ffs(cm) + 63; cm &= cm - 1;
            float4 xb = ((const float4*)S.x)[bb * 16 + ln];
            float wt = S.s1d[bb];
            P.x += wt * xb.x; P.y += wt * xb.y; P.z += wt * xb.z; P.w += wt * xb.w;
        }
        if (mb.w & 2u) {
            P.x += sL0 * paV.x; P.y += sL0 * paV.y; P.z += sL0 * paV.z; P.w += sL0 * paV.w;
        }
        if (mb.w & 1u) {
            P.x += sU * yU.x; P.y += sU * yU.y; P.z += sU * yU.z; P.w += sU * yU.w;
        }

        float sm = ma.x, c = ma.y;

        float g1 = fmaxf(sm * P.x, 0.f) * w2v.x + fmaxf(sm * P.y, 0.f) * w2v.y
                 + fmaxf(sm * P.z, 0.f) * w2v.z + fmaxf(sm * P.w, 0.f) * w2v.w;
        float g2 = fmaxf(sm * (P.x + c * dv.x), 0.f) * w2v.x
                 + fmaxf(sm * (P.y + c * dv.y), 0.f) * w2v.y
                 + fmaxf(sm * (P.z + c * dv.z), 0.f) * w2v.z
                 + fmaxf(sm * (P.w + c * dv.w), 0.f) * w2v.w;

        float coef = act ? ma.z : 0.f;
        acc1 += coef * g1;
        acc2 += coef * g2;
    }

#pragma unroll
    for (int off = 16; off; off >>= 1) {
        acc1 += __shfl_xor_sync(0xffffffffu, acc1, off);
        acc2 += __shfl_xor_sync(0xffffffffu, acc2, off);
    }
    if (lane == 0) {
        out[L * NN + U] = acc1;
        out[U * NN + L] = acc2;
    }
}

extern "C" void kernel_launch(void* const* d_in, const int* in_sizes, int n_in,
                              void* d_out, int out_size) {
    const float* z   = (const float*)d_in[0];
    const float* adj = (const float*)d_in[1];
    const float* W1  = (const float*)d_in[2];
    const float* W2  = (const float*)d_in[3];
    float* out = (float*)d_out;

    reset_kernel<<<1, 128>>>();
    mega_kernel<<<GRID_TOTAL, TPB>>>(z, adj, W1, W2, out);
}